// round 2
// baseline (speedup 1.0000x reference)
#include <cuda_runtime.h>

#define Nn 50000
#define Ee 800000
#define ET 850000            // Ee + Nn self loops
#define F1 256               // HEADS*HID
#define HID 64
#define HEADS 4
#define Gg 64
#define SLOPE 0.2f
#define NBLK 49              // ceil(Nn/1024)

// ---------------- static device scratch (no allocations) ----------------
__device__ __align__(16) float d_xp1[Nn * F1];
__device__ __align__(16) float d_es1[Nn * HEADS];
__device__ __align__(16) float d_ed1[Nn * HEADS];
__device__ __align__(16) float d_elist[(size_t)ET * HEADS];
__device__ __align__(16) float d_h1[Nn * F1];
__device__ __align__(16) float d_xp2[Nn * HID];
__device__ float d_es2[Nn];
__device__ float d_ed2[Nn];
__device__ float d_e2[ET];
__device__ __align__(16) float d_h2[Nn * HID];
__device__ int   d_deg[Nn];
__device__ int   d_off[Nn + 1];
__device__ int   d_cur[Nn];
__device__ int   d_ssrc[ET];
__device__ int   d_bsum[64];
__device__ float d_pool[Gg * HID];
__device__ float d_cnt[Gg];
__device__ int   d_is64;

// index loader robust to int32-vs-int64 (JAX x64-disabled downcasts int64->int32)
__device__ __forceinline__ int ld_idx(const void* p, long long i, int is64) {
    return is64 ? (int)((const long long*)p)[i] : ((const int*)p)[i];
}

// ---------------- dtype detect ----------------
__global__ void k_detect(const int* __restrict__ ei32) {
    int t = threadIdx.x;
    int nz = 0;
    for (int k = t; k < 256; k += 32) nz |= ei32[2 * k + 1];
#pragma unroll
    for (int o = 16; o > 0; o >>= 1) nz |= __shfl_xor_sync(0xffffffffu, nz, o);
    if (t == 0) d_is64 = (nz == 0) ? 1 : 0;
}

// ---------------- init ----------------
__global__ void k_init() {
    int i = blockIdx.x * blockDim.x + threadIdx.x;
    if (i < Nn) d_deg[i] = 0;
    if (i < Gg * HID) d_pool[i] = 0.f;
    if (i < Gg) d_cnt[i] = 0.f;
}

// ---------------- CSR build ----------------
__global__ void k_count(const void* __restrict__ ei) {
    int i = blockIdx.x * blockDim.x + threadIdx.x;
    if (i >= ET) return;
    int is64 = d_is64;
    int dst = (i < Ee) ? ld_idx(ei, (long long)Ee + i, is64) : (i - Ee);
    if ((unsigned)dst >= Nn) return;
    atomicAdd(&d_deg[dst], 1);
}

__global__ void k_scan1() {
    __shared__ int sh[256];
    int base = blockIdx.x * 1024;
    int t = threadIdx.x;
    int s = 0;
#pragma unroll
    for (int k = 0; k < 4; k++) {
        int i = base + k * 256 + t;
        s += (i < Nn) ? d_deg[i] : 0;
    }
    sh[t] = s;
    __syncthreads();
    for (int d = 128; d > 0; d >>= 1) {
        if (t < d) sh[t] += sh[t + d];
        __syncthreads();
    }
    if (t == 0) d_bsum[blockIdx.x] = sh[0];
}

__global__ void k_scan2() {
    int run = 0;
    for (int b = 0; b < NBLK; b++) {
        int v = d_bsum[b];
        d_bsum[b] = run;
        run += v;
    }
    d_off[Nn] = run;
}

__global__ void k_scan3() {
    __shared__ int sh[256];
    int base = blockIdx.x * 1024;
    int t = threadIdx.x;
    int v[4];
#pragma unroll
    for (int k = 0; k < 4; k++) {
        int i = base + t * 4 + k;
        v[k] = (i < Nn) ? d_deg[i] : 0;
    }
    int tot = v[0] + v[1] + v[2] + v[3];
    sh[t] = tot;
    __syncthreads();
    for (int d = 1; d < 256; d <<= 1) {
        int add = (t >= d) ? sh[t - d] : 0;
        __syncthreads();
        sh[t] += add;
        __syncthreads();
    }
    int excl = sh[t] - tot;
    int boff = d_bsum[blockIdx.x];
    int run = boff + excl;
#pragma unroll
    for (int k = 0; k < 4; k++) {
        int i = base + t * 4 + k;
        if (i < Nn) {
            d_off[i] = run;
            d_cur[i] = run;
        }
        run += v[k];
    }
}

__global__ void k_fill(const void* __restrict__ ei) {
    int i = blockIdx.x * blockDim.x + threadIdx.x;
    if (i >= ET) return;
    int is64 = d_is64;
    int src, dst;
    if (i < Ee) {
        src = ld_idx(ei, i, is64);
        dst = ld_idx(ei, (long long)Ee + i, is64);
    } else {
        src = i - Ee; dst = i - Ee;
    }
    if ((unsigned)src >= Nn || (unsigned)dst >= Nn) return;
    int p = atomicAdd(&d_cur[dst], 1);
    if ((unsigned)p < ET) d_ssrc[p] = src;
}

// ---------------- layer 1 GEMM: xp1 = x @ W1, plus attention dots ----------------
__global__ void k_gemm1(const float* __restrict__ x, const float* __restrict__ W1,
                        const float* __restrict__ a1s, const float* __restrict__ a1d) {
    __shared__ float xs[64];
    __shared__ float reds[8], redd[8];
    int t = threadIdx.x;
    for (int n = blockIdx.x; n < Nn; n += gridDim.x) {
        if (t < 64) xs[t] = x[n * 64 + t];
        __syncthreads();
        float acc = 0.f;
#pragma unroll
        for (int k = 0; k < 64; k++) acc = fmaf(xs[k], W1[k * 256 + t], acc);
        d_xp1[n * 256 + t] = acc;
        float ps = acc * a1s[t];
        float pd = acc * a1d[t];
#pragma unroll
        for (int o = 16; o > 0; o >>= 1) {
            ps += __shfl_down_sync(0xffffffffu, ps, o);
            pd += __shfl_down_sync(0xffffffffu, pd, o);
        }
        if ((t & 31) == 0) { reds[t >> 5] = ps; redd[t >> 5] = pd; }
        __syncthreads();
        if (t < 4) {
            d_es1[n * 4 + t] = reds[2 * t] + reds[2 * t + 1];
            d_ed1[n * 4 + t] = redd[2 * t] + redd[2 * t + 1];
        }
        __syncthreads();
    }
}

// ---------------- layer 1 per-destination-node: softmax + aggregate + ELU ----------------
__device__ __forceinline__ void onl(float& m, float& s, float e) {
    if (e > m) { s = s * __expf(m - e) + 1.f; m = e; }
    else       { s += __expf(e - m); }
}

__global__ void k_l1node(const float* __restrict__ b1) {
    int w = (blockIdx.x * blockDim.x + threadIdx.x) >> 5;
    int lane = threadIdx.x & 31;
    if (w >= Nn) return;
    int n = w;
    int beg = d_off[n], end = d_off[n + 1];
    float4 ed = *(const float4*)&d_ed1[n * 4];
    float m0 = -1e30f, m1 = -1e30f, m2 = -1e30f, m3 = -1e30f;
    float s0 = 0.f, s1 = 0.f, s2 = 0.f, s3 = 0.f;
    float4* elp = (float4*)d_elist;
    for (int j = beg + lane; j < end; j += 32) {
        int sc = d_ssrc[j];
        float4 es = *(const float4*)&d_es1[sc * 4];
        float e0 = es.x + ed.x; e0 = e0 > 0.f ? e0 : SLOPE * e0;
        float e1 = es.y + ed.y; e1 = e1 > 0.f ? e1 : SLOPE * e1;
        float e2 = es.z + ed.z; e2 = e2 > 0.f ? e2 : SLOPE * e2;
        float e3 = es.w + ed.w; e3 = e3 > 0.f ? e3 : SLOPE * e3;
        elp[j] = make_float4(e0, e1, e2, e3);
        onl(m0, s0, e0); onl(m1, s1, e1); onl(m2, s2, e2); onl(m3, s3, e3);
    }
#pragma unroll
    for (int o = 16; o > 0; o >>= 1) {
        float om, os, nm;
        om = __shfl_xor_sync(0xffffffffu, m0, o); os = __shfl_xor_sync(0xffffffffu, s0, o);
        nm = fmaxf(m0, om); s0 = s0 * __expf(m0 - nm) + os * __expf(om - nm); m0 = nm;
        om = __shfl_xor_sync(0xffffffffu, m1, o); os = __shfl_xor_sync(0xffffffffu, s1, o);
        nm = fmaxf(m1, om); s1 = s1 * __expf(m1 - nm) + os * __expf(om - nm); m1 = nm;
        om = __shfl_xor_sync(0xffffffffu, m2, o); os = __shfl_xor_sync(0xffffffffu, s2, o);
        nm = fmaxf(m2, om); s2 = s2 * __expf(m2 - nm) + os * __expf(om - nm); m2 = nm;
        om = __shfl_xor_sync(0xffffffffu, m3, o); os = __shfl_xor_sync(0xffffffffu, s3, o);
        nm = fmaxf(m3, om); s3 = s3 * __expf(m3 - nm) + os * __expf(om - nm); m3 = nm;
    }
    int h = lane >> 3;
    float mh = (h == 0) ? m0 : (h == 1) ? m1 : (h == 2) ? m2 : m3;
    float sh = (h == 0) ? s0 : (h == 1) ? s1 : (h == 2) ? s2 : s3;
    float ih = 1.f / sh;
    int cb = lane * 8;
    float a0 = 0, a1 = 0, a2 = 0, a3 = 0, a4 = 0, a5 = 0, a6 = 0, a7 = 0;
    const float4* elc = (const float4*)d_elist;

    int j = beg;
    for (; j + 1 < end; j += 2) {
        int scA = d_ssrc[j], scB = d_ssrc[j + 1];
        float4 eA = elc[j], eB = elc[j + 1];
        const float4* rA = (const float4*)&d_xp1[scA * 256 + cb];
        const float4* rB = (const float4*)&d_xp1[scB * 256 + cb];
        float4 vA0 = rA[0], vA1 = rA[1];
        float4 vB0 = rB[0], vB1 = rB[1];
        float ehA = (h == 0) ? eA.x : (h == 1) ? eA.y : (h == 2) ? eA.z : eA.w;
        float ehB = (h == 0) ? eB.x : (h == 1) ? eB.y : (h == 2) ? eB.z : eB.w;
        float alA = __expf(ehA - mh) * ih;
        float alB = __expf(ehB - mh) * ih;
        a0 = fmaf(alA, vA0.x, a0); a1 = fmaf(alA, vA0.y, a1);
        a2 = fmaf(alA, vA0.z, a2); a3 = fmaf(alA, vA0.w, a3);
        a4 = fmaf(alA, vA1.x, a4); a5 = fmaf(alA, vA1.y, a5);
        a6 = fmaf(alA, vA1.z, a6); a7 = fmaf(alA, vA1.w, a7);
        a0 = fmaf(alB, vB0.x, a0); a1 = fmaf(alB, vB0.y, a1);
        a2 = fmaf(alB, vB0.z, a2); a3 = fmaf(alB, vB0.w, a3);
        a4 = fmaf(alB, vB1.x, a4); a5 = fmaf(alB, vB1.y, a5);
        a6 = fmaf(alB, vB1.z, a6); a7 = fmaf(alB, vB1.w, a7);
    }
    if (j < end) {
        int sc = d_ssrc[j];
        float4 e4 = elc[j];
        const float4* r = (const float4*)&d_xp1[sc * 256 + cb];
        float4 v0 = r[0], v1 = r[1];
        float eh = (h == 0) ? e4.x : (h == 1) ? e4.y : (h == 2) ? e4.z : e4.w;
        float al = __expf(eh - mh) * ih;
        a0 = fmaf(al, v0.x, a0); a1 = fmaf(al, v0.y, a1);
        a2 = fmaf(al, v0.z, a2); a3 = fmaf(al, v0.w, a3);
        a4 = fmaf(al, v1.x, a4); a5 = fmaf(al, v1.y, a5);
        a6 = fmaf(al, v1.z, a6); a7 = fmaf(al, v1.w, a7);
    }
    float o0 = a0 + b1[cb + 0], o1 = a1 + b1[cb + 1], o2 = a2 + b1[cb + 2], o3 = a3 + b1[cb + 3];
    float o4 = a4 + b1[cb + 4], o5 = a5 + b1[cb + 5], o6 = a6 + b1[cb + 6], o7 = a7 + b1[cb + 7];
    o0 = o0 > 0.f ? o0 : __expf(o0) - 1.f;
    o1 = o1 > 0.f ? o1 : __expf(o1) - 1.f;
    o2 = o2 > 0.f ? o2 : __expf(o2) - 1.f;
    o3 = o3 > 0.f ? o3 : __expf(o3) - 1.f;
    o4 = o4 > 0.f ? o4 : __expf(o4) - 1.f;
    o5 = o5 > 0.f ? o5 : __expf(o5) - 1.f;
    o6 = o6 > 0.f ? o6 : __expf(o6) - 1.f;
    o7 = o7 > 0.f ? o7 : __expf(o7) - 1.f;
    float4* dst = (float4*)&d_h1[n * 256 + cb];
    dst[0] = make_float4(o0, o1, o2, o3);
    dst[1] = make_float4(o4, o5, o6, o7);
}

// ---------------- layer 2 GEMM: xp2 = h1 @ W2, plus attention dots ----------------
__global__ void k_gemm2(const float* __restrict__ W2,
                        const float* __restrict__ a2s, const float* __restrict__ a2d) {
    __shared__ float hs[4 * 256];
    __shared__ float reds[8], redd[8];
    int t = threadIdx.x;
    int sub = t >> 6;
    int c = t & 63;
    int n0 = blockIdx.x * 4;
    int n = n0 + sub;
    bool ok = n < Nn;
#pragma unroll
    for (int jj = 0; jj < 4; jj++)
        hs[sub * 256 + c + 64 * jj] = ok ? d_h1[n * 256 + c + 64 * jj] : 0.f;
    __syncthreads();
    float acc = 0.f;
#pragma unroll 8
    for (int k = 0; k < 256; k++) acc = fmaf(hs[sub * 256 + k], W2[k * 64 + c], acc);
    if (ok) d_xp2[n * 64 + c] = acc;
    float ps = acc * a2s[c];
    float pd = acc * a2d[c];
#pragma unroll
    for (int o = 16; o > 0; o >>= 1) {
        ps += __shfl_down_sync(0xffffffffu, ps, o);
        pd += __shfl_down_sync(0xffffffffu, pd, o);
    }
    if ((t & 31) == 0) { reds[t >> 5] = ps; redd[t >> 5] = pd; }
    __syncthreads();
    if (t < 4 && (n0 + t) < Nn) {
        d_es2[n0 + t] = reds[2 * t] + reds[2 * t + 1];
        d_ed2[n0 + t] = redd[2 * t] + redd[2 * t + 1];
    }
}

// ---------------- layer 2 per-destination-node ----------------
__global__ void k_l2node(const float* __restrict__ b2) {
    int w = (blockIdx.x * blockDim.x + threadIdx.x) >> 5;
    int lane = threadIdx.x & 31;
    if (w >= Nn) return;
    int n = w;
    int beg = d_off[n], end = d_off[n + 1];
    float edn = d_ed2[n];
    float m = -1e30f, s = 0.f;
    for (int j = beg + lane; j < end; j += 32) {
        int sc = d_ssrc[j];
        float e = d_es2[sc] + edn;
        e = e > 0.f ? e : SLOPE * e;
        d_e2[j] = e;
        onl(m, s, e);
    }
#pragma unroll
    for (int o = 16; o > 0; o >>= 1) {
        float om = __shfl_xor_sync(0xffffffffu, m, o);
        float os = __shfl_xor_sync(0xffffffffu, s, o);
        float nm = fmaxf(m, om);
        s = s * __expf(m - nm) + os * __expf(om - nm);
        m = nm;
    }
    float inv = 1.f / s;
    int cb = lane * 2;
    float a0 = 0.f, a1 = 0.f;
    int j = beg;
    for (; j + 1 < end; j += 2) {
        int scA = d_ssrc[j], scB = d_ssrc[j + 1];
        float eA = d_e2[j], eB = d_e2[j + 1];
        float2 vA = *(const float2*)&d_xp2[scA * 64 + cb];
        float2 vB = *(const float2*)&d_xp2[scB * 64 + cb];
        float alA = __expf(eA - m) * inv;
        float alB = __expf(eB - m) * inv;
        a0 = fmaf(alA, vA.x, a0); a1 = fmaf(alA, vA.y, a1);
        a0 = fmaf(alB, vB.x, a0); a1 = fmaf(alB, vB.y, a1);
    }
    if (j < end) {
        int sc = d_ssrc[j];
        float e = d_e2[j];
        float2 v = *(const float2*)&d_xp2[sc * 64 + cb];
        float al = __expf(e - m) * inv;
        a0 = fmaf(al, v.x, a0); a1 = fmaf(al, v.y, a1);
    }
    float2 outv = make_float2(a0 + b2[cb], a1 + b2[cb + 1]);
    *(float2*)&d_h2[n * 64 + cb] = outv;
}

// ---------------- global mean pool (batch is sorted) ----------------
__global__ void k_pool(const void* __restrict__ batch) {
    int c = threadIdx.x;
    int n0 = blockIdx.x * 256;
    int n1 = n0 + 256;
    if (n1 > Nn) n1 = Nn;
    if (n0 >= Nn) return;
    int is64 = d_is64;
    int cur = ld_idx(batch, n0, is64);
    if ((unsigned)cur >= Gg) cur = 0;
    float acc = 0.f, cc = 0.f;
    for (int n = n0; n < n1; n++) {
        int g = ld_idx(batch, n, is64);
        if ((unsigned)g >= Gg) g = 0;
        if (g != cur) {
            atomicAdd(&d_pool[cur * 64 + c], acc);
            if (c == 0) atomicAdd(&d_cnt[cur], cc);
            acc = 0.f; cc = 0.f; cur = g;
        }
        acc += d_h2[n * 64 + c];
        cc += 1.f;
    }
    atomicAdd(&d_pool[cur * 64 + c], acc);
    if (c == 0) atomicAdd(&d_cnt[cur], cc);
}

// ---------------- MLP head ----------------
__global__ void k_mlp(const float* __restrict__ Wh1, const float* __restrict__ bh1,
                      const float* __restrict__ Wh2, const float* __restrict__ bh2,
                      float* __restrict__ out) {
    int g = threadIdx.x;
    if (g >= Gg) return;
    float invc = 1.f / fmaxf(d_cnt[g], 1.f);
    float p[64];
#pragma unroll
    for (int k = 0; k < 64; k++) p[k] = d_pool[g * 64 + k] * invc;
    float o = bh2[0];
#pragma unroll
    for (int j = 0; j < 16; j++) {
        float z = bh1[j];
#pragma unroll
        for (int k = 0; k < 64; k++) z = fmaf(p[k], Wh1[k * 16 + j], z);
        z = fmaxf(z, 0.f);
        o = fmaf(z, Wh2[j], o);
    }
    out[g] = 1.f / (1.f + __expf(-o));
}

// ---------------- launch ----------------
extern "C" void kernel_launch(void* const* d_in, const int* in_sizes, int n_in,
                              void* d_out, int out_size) {
    const float* x       = (const float*)d_in[0];
    const void* ei       = d_in[1];
    const void* bat      = d_in[2];
    const float* W1  = (const float*)d_in[3];
    const float* a1s = (const float*)d_in[4];
    const float* a1d = (const float*)d_in[5];
    const float* b1  = (const float*)d_in[6];
    const float* W2  = (const float*)d_in[7];
    const float* a2s = (const float*)d_in[8];
    const float* a2d = (const float*)d_in[9];
    const float* b2  = (const float*)d_in[10];
    const float* Wh1 = (const float*)d_in[11];
    const float* bh1 = (const float*)d_in[12];
    const float* Wh2 = (const float*)d_in[13];
    const float* bh2 = (const float*)d_in[14];
    float* out = (float*)d_out;

    k_detect<<<1, 32>>>((const int*)ei);
    k_init<<<(Nn + 255) / 256, 256>>>();
    k_count<<<(ET + 255) / 256, 256>>>(ei);
    k_scan1<<<NBLK, 256>>>();
    k_scan2<<<1, 1>>>();
    k_scan3<<<NBLK, 256>>>();
    k_fill<<<(ET + 255) / 256, 256>>>(ei);
    k_gemm1<<<4096, 256>>>(x, W1, a1s, a1d);
    k_l1node<<<(Nn + 7) / 8, 256>>>(b1);
    k_gemm2<<<(Nn + 3) / 4, 256>>>(W2, a2s, a2d);
    k_l2node<<<(Nn + 7) / 8, 256>>>(b2);
    k_pool<<<(Nn + 255) / 256, 64>>>(bat);
    k_mlp<<<1, 64>>>(Wh1, bh1, Wh2, bh2, out);
}